// round 13
// baseline (speedup 1.0000x reference)
#include <cuda_runtime.h>
#include <cstdint>

#define B_DIM 32
#define S_LEN 2048
#define I_DIM 256
#define H_DIM 256
#define CHUNK 128
#define N_CHUNKS (S_LEN / CHUNK)          // 16
#define REC_Y 32                          // recurrence blocks: y in [0,32)
#define GEMM_MT (B_DIM * N_CHUNKS)        // 512 m-tiles

// chunk-ready flags: flag[row][chunk] counts finished N-tiles (2 = ready)
__device__ int g_flags[B_DIM][N_CHUNKS];

// ---------------------------------------------------------------------------
// helpers
// ---------------------------------------------------------------------------
__device__ __forceinline__ unsigned long long ffma2(unsigned long long a,
                                                    unsigned long long b,
                                                    unsigned long long c) {
    unsigned long long d;
    asm("fma.rn.f32x2 %0, %1, %2, %3;" : "=l"(d) : "l"(a), "l"(b), "l"(c));
    return d;
}
__device__ __forceinline__ unsigned long long pack2(float x, float y) {
    unsigned long long d;
    asm("mov.b64 %0, {%1, %2};" : "=l"(d) : "f"(x), "f"(y));
    return d;
}
__device__ __forceinline__ float2 unpack2(unsigned long long v) {
    float2 r;
    asm("mov.b64 {%0, %1}, %2;" : "=f"(r.x), "=f"(r.y) : "l"(v));
    return r;
}
__device__ __forceinline__ uint32_t smem_u32(const void* p) {
    uint32_t a;
    asm("{ .reg .u64 t; cvta.to.shared.u64 t, %1; cvt.u32.u64 %0, t; }"
        : "=r"(a) : "l"(p));
    return a;
}
__device__ __forceinline__ uint32_t mapa_u32(uint32_t a, uint32_t rank) {
    uint32_t d;
    asm("mapa.shared::cluster.u32 %0, %1, %2;" : "=r"(d) : "r"(a), "r"(rank));
    return d;
}
__device__ __forceinline__ void mbar_init(uint32_t mbar, uint32_t count) {
    asm volatile("mbarrier.init.shared.b64 [%0], %1;" :: "r"(mbar), "r"(count) : "memory");
}
__device__ __forceinline__ void mbar_expect_tx(uint32_t mbar, uint32_t bytes) {
    asm volatile("mbarrier.arrive.expect_tx.shared.b64 _, [%0], %1;"
                 :: "r"(mbar), "r"(bytes) : "memory");
}
__device__ __forceinline__ void mbar_wait(uint32_t mbar, uint32_t parity) {
    asm volatile(
        "{\n\t.reg .pred P;\n\t"
        "WL%=:\n\t"
        "mbarrier.try_wait.parity.acquire.cta.shared::cta.b64 P, [%0], %1, 0x989680;\n\t"
        "@!P bra WL%=;\n\t}"
        :: "r"(mbar), "r"(parity) : "memory");
}
__device__ __forceinline__ void st_async_f32(uint32_t raddr, float v, uint32_t rmbar) {
    asm volatile(
        "st.async.shared::cluster.mbarrier::complete_tx::bytes.f32 [%0], %1, [%2];"
        :: "r"(raddr), "f"(v), "r"(rmbar) : "memory");
}
__device__ __forceinline__ float tanh_fast(float x) {
    float r;
    asm("tanh.approx.f32 %0, %1;" : "=f"(r) : "f"(x));
    return r;
}

// ---------------------------------------------------------------------------
// flag reset (graph replays reuse device globals -> reset every launch)
// ---------------------------------------------------------------------------
__global__ void flag_init_kernel() {
    int i = threadIdx.x;
    if (i < B_DIM * N_CHUNKS) ((int*)g_flags)[i] = 0;
}

// ---------------------------------------------------------------------------
// Fused kernel: grid (2, REC_Y + GEMM_MT), 256 threads, cluster (2,1,1).
//   y <  REC_Y : recurrence cluster for batch row y (rank = x)
//   y >= REC_Y : GEMM block for m-tile (y-REC_Y) [chunk-major], n-tile x
// ---------------------------------------------------------------------------
__global__ __launch_bounds__(256, 1) __cluster_dims__(2, 1, 1)
void srnn_fused_kernel(const float* __restrict__ x,
                       const float* __restrict__ Wx_w,
                       const float* __restrict__ Wx_b,
                       const float* __restrict__ Wh,
                       float* __restrict__ out) {
    __shared__ __align__(16) unsigned char arena[16384];
    const int t = threadIdx.x;

    if (blockIdx.y >= REC_Y) {
        // =================== GEMM: xw tile into outputs region ===========
        float (*As)[128] = (float(*)[128])(arena);
        float (*Bs)[128] = (float(*)[128])(arena + 8192);

        const int y2      = blockIdx.y - REC_Y;
        const int s_chunk = y2 >> 5;           // 0..15  (chunk-major order)
        const int b       = y2 & 31;           // 0..31
        const long bm = (long)b * S_LEN + (long)s_chunk * CHUNK;
        const long bn = (long)blockIdx.x * 128;

        const int tx = t & 15;
        const int ty = t >> 4;
        const float* Ab = x + bm * I_DIM;
        const float* Wb = Wx_w + bn * I_DIM;

        unsigned long long acc[8][4];
#pragma unroll
        for (int i = 0; i < 8; i++)
#pragma unroll
            for (int j = 0; j < 4; j++) acc[i][j] = 0ull;

        for (int k0 = 0; k0 < I_DIM; k0 += 16) {
#pragma unroll
            for (int f = t; f < 512; f += 256) {
                int row = f >> 2, kq = f & 3;
                float4 va = *(const float4*)(Ab + (long)row * I_DIM + k0 + kq * 4);
                As[kq * 4 + 0][row] = va.x; As[kq * 4 + 1][row] = va.y;
                As[kq * 4 + 2][row] = va.z; As[kq * 4 + 3][row] = va.w;
                float4 vw = *(const float4*)(Wb + (long)row * I_DIM + k0 + kq * 4);
                Bs[kq * 4 + 0][row] = vw.x; Bs[kq * 4 + 1][row] = vw.y;
                Bs[kq * 4 + 2][row] = vw.z; Bs[kq * 4 + 3][row] = vw.w;
            }
            __syncthreads();
#pragma unroll
            for (int k = 0; k < 16; k++) {
                const float4* As4 = (const float4*)&As[k][0];
                const ulonglong2* Bs2 = (const ulonglong2*)&Bs[k][0];
                float4 a0 = As4[ty * 2], a1 = As4[ty * 2 + 1];
                ulonglong2 bA = Bs2[tx * 2], bB = Bs2[tx * 2 + 1];
                unsigned long long bp[4] = {bA.x, bA.y, bB.x, bB.y};
                float av[8] = {a0.x, a0.y, a0.z, a0.w, a1.x, a1.y, a1.z, a1.w};
#pragma unroll
                for (int i = 0; i < 8; i++) {
                    unsigned long long ap = pack2(av[i], av[i]);
#pragma unroll
                    for (int j = 0; j < 4; j++) acc[i][j] = ffma2(ap, bp[j], acc[i][j]);
                }
            }
            __syncthreads();
        }

        float bv[8];
#pragma unroll
        for (int j = 0; j < 8; j++) bv[j] = Wx_b[bn + tx * 8 + j];
#pragma unroll
        for (int i = 0; i < 8; i++) {
            long m = bm + ty * 8 + i;
            float* Crow = out + m * (long)H_DIM + bn + tx * 8;
            float2 c0 = unpack2(acc[i][0]), c1 = unpack2(acc[i][1]);
            float2 c2 = unpack2(acc[i][2]), c3 = unpack2(acc[i][3]);
            *(float4*)(Crow)     = make_float4(c0.x + bv[0], c0.y + bv[1], c1.x + bv[2], c1.y + bv[3]);
            *(float4*)(Crow + 4) = make_float4(c2.x + bv[4], c2.y + bv[5], c3.x + bv[6], c3.y + bv[7]);
        }

        __threadfence();
        __syncthreads();
        if (t == 0) atomicAdd(&g_flags[b][s_chunk], 1);
        return;
    }

    // ====================== recurrence ====================================
    // h stored INTERLEAVED: pos(k) = ((k&63)>>2)*8 + ((k>>6)<<2) + (k&3)
    // so kc0/kc1 lanes' 16B reads sit 16B apart -> one L1 wavefront per LDS.
    float (*hS)[128]   = (float(*)[128])(arena);          // [buf][pos] my h half
    float (*pbuf)[256] = (float(*)[256])(arena + 1024);   // [buf][jl*2+kc] partials
    unsigned long long* mbarp = (unsigned long long*)(arena + 4096);

    const int rank = blockIdx.x;
    const int row  = blockIdx.y;
    const int jl   = t >> 1;
    const int kc   = t & 1;
    const int jg   = rank * 128 + jl;
    const int jp   = (rank ^ 1) * 128 + jl;
    // interleaved write position for my h value (k = jl)
    const int hpos = ((jl & 63) >> 2) * 8 + ((jl >> 6) << 2) + (jl & 3);

    unsigned long long wPA[16], wPB[16], wLA[16], wLB[16];
    {
        const float* wp = Wh + (long)jp * H_DIM + (rank * 128 + kc * 64);
        const float* wl = Wh + (long)jg * H_DIM + (rank * 128 + kc * 64);
#pragma unroll
        for (int u = 0; u < 16; u++) {
            ulonglong2 a = *(const ulonglong2*)(wp + u * 4);
            wPA[u] = a.x; wPB[u] = a.y;
            ulonglong2 b2 = *(const ulonglong2*)(wl + u * 4);
            wLA[u] = b2.x; wLB[u] = b2.y;
        }
    }

    const uint32_t mb0 = smem_u32(&mbarp[0]);
    const uint32_t mb1 = smem_u32(&mbarp[1]);

    if (t == 0) {
        mbar_init(mb0, 1);
        mbar_init(mb1, 1);
        mbar_expect_tx(mb0, 1024);
        mbar_expect_tx(mb1, 1024);
    }
    if (t < 128) hS[0][t] = 0.0f;     // h0 = 0 (zero in any layout)
    __syncthreads();
    asm volatile("barrier.cluster.arrive.aligned;" ::: "memory");
    asm volatile("barrier.cluster.wait.aligned;" ::: "memory");

    const uint32_t prB0 = mapa_u32(smem_u32(&pbuf[0][0]), rank ^ 1);
    const uint32_t prB1 = mapa_u32(smem_u32(&pbuf[1][0]), rank ^ 1);
    const uint32_t pmb0 = mapa_u32(mb0, rank ^ 1);
    const uint32_t pmb1 = mapa_u32(mb1, rank ^ 1);

    // EVERY lane ships its own 64-k partial: offset = t*4 (jl*8 + kc*4)
    const uint32_t shipoff = (uint32_t)t * 4u;

    // wait for xw chunk 0 (t0 spins, block follows)
    {
        if (t == 0) {
            volatile int* f = &g_flags[row][0];
            while (*f < 2) __nanosleep(512);
        }
        __syncthreads();
        __threadfence();
    }

    float* xwp = out + (long)row * S_LEN * H_DIM + jg;
    float xw_next = xwp[0];

    for (int step = 0; step < S_LEN; step++) {
        const int b = step & 1;
        float xw_cur = xw_next;

        // ---- P phase FIRST: 16 LDS + 32 FMA, then ship immediately ----
        const float* hb = &hS[b][0];
        unsigned long long pA = 0ull, pB = 0ull;
#pragma unroll
        for (int u = 0; u < 16; u++) {
            ulonglong2 hv = *(const ulonglong2*)(hb + u * 8 + kc * 4);
            pA = ffma2(hv.x, wPA[u], pA);
            pB = ffma2(hv.y, wPB[u], pB);
        }
        float2 gp0 = unpack2(pA), gp1 = unpack2(pB);
        float P = (gp0.x + gp0.y) + (gp1.x + gp1.y);

        st_async_f32((b ? prB1 : prB0) + shipoff, P, b ? pmb1 : pmb0);

        // ---- L phase (in the transit shadow; st.async clobber blocks CSE) ----
        unsigned long long lA = 0ull, lB = 0ull;
#pragma unroll
        for (int u = 0; u < 16; u++) {
            ulonglong2 hv = *(const ulonglong2*)(hb + u * 8 + kc * 4);
            lA = ffma2(hv.x, wLA[u], lA);
            lB = ffma2(hv.y, wLB[u], lB);
        }
        float2 gl0 = unpack2(lA), gl1 = unpack2(lB);
        float L = (gl0.x + gl0.y) + (gl1.x + gl1.y);
        L += __shfl_xor_sync(0xffffffffu, L, 1);
        const float base = L + xw_cur;

        // xw prefetch + chunk gate (also inside the transit shadow)
        if (step + 1 < S_LEN) {
            if (((step + 1) & (CHUNK - 1)) == 0) {      // entering a new chunk
                if (t == 0) {
                    volatile int* f = &g_flags[row][(step + 1) >> 7];
                    while (*f < 2) __nanosleep(512);
                }
                __syncthreads();
                __threadfence();
            }
            xw_next = xwp[(long)(step + 1) * H_DIM];
        }

        // ---- wait for peer's partials, finish the step ----
        mbar_wait(b ? mb1 : mb0, (step >> 1) & 1);
        if (t == 3) mbar_expect_tx(b ? mb1 : mb0, 1024); // re-arm for step+2

        float2 pp = *(const float2*)(&pbuf[b][jl * 2]);  // both kc partials
        float v = tanh_fast(base + pp.x + pp.y);

        if (kc == 0) {
            hS[b ^ 1][hpos] = v;                         // interleaved store
        } else {
            xwp[(long)step * H_DIM] = v;                 // in-place output
            if (step == S_LEN - 1)
                out[(long)B_DIM * S_LEN * H_DIM + (long)row * H_DIM + jg] = v;
        }

        __syncthreads();
    }

    asm volatile("barrier.cluster.arrive.aligned;" ::: "memory");
    asm volatile("barrier.cluster.wait.aligned;" ::: "memory");
}

// ---------------------------------------------------------------------------
// Launch
// ---------------------------------------------------------------------------
extern "C" void kernel_launch(void* const* d_in, const int* in_sizes, int n_in,
                              void* d_out, int out_size) {
    const float* x    = (const float*)d_in[0];  // [B,S,I]
    const float* Wx_w = (const float*)d_in[1];  // [H,I]
    const float* Wx_b = (const float*)d_in[2];  // [H]
    const float* Wh_w = (const float*)d_in[3];  // [H,H]
    float* out = (float*)d_out;                 // [B,S,H] ++ [B,H]

    flag_init_kernel<<<1, 512>>>();

    dim3 g(2, REC_Y + GEMM_MT);                 // (2, 544)
    srnn_fused_kernel<<<g, 256>>>(x, Wx_w, Wx_b, Wh_w, out);
}

// round 15
// speedup vs baseline: 1.0510x; 1.0510x over previous
#include <cuda_runtime.h>
#include <cstdint>

#define B_DIM 32
#define S_LEN 2048
#define I_DIM 256
#define H_DIM 256
#define CHUNK 128
#define N_CHUNKS (S_LEN / CHUNK)          // 16
#define REC_Y 32                          // recurrence blocks: y in [0,32)
#define GEMM_MT (B_DIM * N_CHUNKS)        // 512 m-tiles

// chunk-ready flags: flag[row][chunk] counts finished N-tiles (2 = ready)
__device__ int g_flags[B_DIM][N_CHUNKS];

// ---------------------------------------------------------------------------
// helpers
// ---------------------------------------------------------------------------
__device__ __forceinline__ unsigned long long ffma2(unsigned long long a,
                                                    unsigned long long b,
                                                    unsigned long long c) {
    unsigned long long d;
    asm("fma.rn.f32x2 %0, %1, %2, %3;" : "=l"(d) : "l"(a), "l"(b), "l"(c));
    return d;
}
__device__ __forceinline__ unsigned long long pack2(float x, float y) {
    unsigned long long d;
    asm("mov.b64 %0, {%1, %2};" : "=l"(d) : "f"(x), "f"(y));
    return d;
}
__device__ __forceinline__ float2 unpack2(unsigned long long v) {
    float2 r;
    asm("mov.b64 {%0, %1}, %2;" : "=f"(r.x), "=f"(r.y) : "l"(v));
    return r;
}
__device__ __forceinline__ uint32_t smem_u32(const void* p) {
    uint32_t a;
    asm("{ .reg .u64 t; cvta.to.shared.u64 t, %1; cvt.u32.u64 %0, t; }"
        : "=r"(a) : "l"(p));
    return a;
}
__device__ __forceinline__ uint32_t mapa_u32(uint32_t a, uint32_t rank) {
    uint32_t d;
    asm("mapa.shared::cluster.u32 %0, %1, %2;" : "=r"(d) : "r"(a), "r"(rank));
    return d;
}
__device__ __forceinline__ void mbar_init(uint32_t mbar, uint32_t count) {
    asm volatile("mbarrier.init.shared.b64 [%0], %1;" :: "r"(mbar), "r"(count) : "memory");
}
__device__ __forceinline__ void mbar_expect_tx(uint32_t mbar, uint32_t bytes) {
    asm volatile("mbarrier.arrive.expect_tx.shared.b64 _, [%0], %1;"
                 :: "r"(mbar), "r"(bytes) : "memory");
}
__device__ __forceinline__ void mbar_wait(uint32_t mbar, uint32_t parity) {
    asm volatile(
        "{\n\t.reg .pred P;\n\t"
        "WL%=:\n\t"
        "mbarrier.try_wait.parity.acquire.cta.shared::cta.b64 P, [%0], %1, 0x989680;\n\t"
        "@!P bra WL%=;\n\t}"
        :: "r"(mbar), "r"(parity) : "memory");
}
__device__ __forceinline__ void st_async_f32(uint32_t raddr, float v, uint32_t rmbar) {
    asm volatile(
        "st.async.shared::cluster.mbarrier::complete_tx::bytes.f32 [%0], %1, [%2];"
        :: "r"(raddr), "f"(v), "r"(rmbar) : "memory");
}
__device__ __forceinline__ float tanh_fast(float x) {
    float r;
    asm("tanh.approx.f32 %0, %1;" : "=f"(r) : "f"(x));
    return r;
}

// ---------------------------------------------------------------------------
// flag reset (graph replays reuse device globals -> reset every launch)
// ---------------------------------------------------------------------------
__global__ void flag_init_kernel() {
    int i = threadIdx.x;
    if (i < B_DIM * N_CHUNKS) ((int*)g_flags)[i] = 0;
}

// ---------------------------------------------------------------------------
// Fused kernel: grid (2, REC_Y + GEMM_MT), 256 threads, cluster (2,1,1).
//   y <  REC_Y : recurrence cluster for batch row y (rank = x)
//   y >= REC_Y : GEMM block for m-tile (y-REC_Y) [chunk-major], n-tile x
//
// Recurrence uses WARP SPECIALIZATION:
//   threads 0..127  (P-warps): full 128-k dot for PEER output jl from local
//                              h (broadcast LDS), ship immediately.
//   threads 128..255 (L-warps): full 128-k dot for OWN output jl, then wait
//                              for peer partial, tanh, store h + output.
// ---------------------------------------------------------------------------
__global__ __launch_bounds__(256, 1) __cluster_dims__(2, 1, 1)
void srnn_fused_kernel(const float* __restrict__ x,
                       const float* __restrict__ Wx_w,
                       const float* __restrict__ Wx_b,
                       const float* __restrict__ Wh,
                       float* __restrict__ out) {
    __shared__ __align__(16) unsigned char arena[16384];
    const int t = threadIdx.x;

    if (blockIdx.y >= REC_Y) {
        // =================== GEMM: xw tile into outputs region ===========
        float (*As)[128] = (float(*)[128])(arena);
        float (*Bs)[128] = (float(*)[128])(arena + 8192);

        const int y2      = blockIdx.y - REC_Y;
        const int s_chunk = y2 >> 5;           // 0..15  (chunk-major order)
        const int b       = y2 & 31;           // 0..31
        const long bm = (long)b * S_LEN + (long)s_chunk * CHUNK;
        const long bn = (long)blockIdx.x * 128;

        const int tx = t & 15;
        const int ty = t >> 4;
        const float* Ab = x + bm * I_DIM;
        const float* Wb = Wx_w + bn * I_DIM;

        unsigned long long acc[8][4];
#pragma unroll
        for (int i = 0; i < 8; i++)
#pragma unroll
            for (int j = 0; j < 4; j++) acc[i][j] = 0ull;

        for (int k0 = 0; k0 < I_DIM; k0 += 16) {
#pragma unroll
            for (int f = t; f < 512; f += 256) {
                int row = f >> 2, kq = f & 3;
                float4 va = *(const float4*)(Ab + (long)row * I_DIM + k0 + kq * 4);
                As[kq * 4 + 0][row] = va.x; As[kq * 4 + 1][row] = va.y;
                As[kq * 4 + 2][row] = va.z; As[kq * 4 + 3][row] = va.w;
                float4 vw = *(const float4*)(Wb + (long)row * I_DIM + k0 + kq * 4);
                Bs[kq * 4 + 0][row] = vw.x; Bs[kq * 4 + 1][row] = vw.y;
                Bs[kq * 4 + 2][row] = vw.z; Bs[kq * 4 + 3][row] = vw.w;
            }
            __syncthreads();
#pragma unroll
            for (int k = 0; k < 16; k++) {
                const float4* As4 = (const float4*)&As[k][0];
                const ulonglong2* Bs2 = (const ulonglong2*)&Bs[k][0];
                float4 a0 = As4[ty * 2], a1 = As4[ty * 2 + 1];
                ulonglong2 bA = Bs2[tx * 2], bB = Bs2[tx * 2 + 1];
                unsigned long long bp[4] = {bA.x, bA.y, bB.x, bB.y};
                float av[8] = {a0.x, a0.y, a0.z, a0.w, a1.x, a1.y, a1.z, a1.w};
#pragma unroll
                for (int i = 0; i < 8; i++) {
                    unsigned long long ap = pack2(av[i], av[i]);
#pragma unroll
                    for (int j = 0; j < 4; j++) acc[i][j] = ffma2(ap, bp[j], acc[i][j]);
                }
            }
            __syncthreads();
        }

        float bv[8];
#pragma unroll
        for (int j = 0; j < 8; j++) bv[j] = Wx_b[bn + tx * 8 + j];
#pragma unroll
        for (int i = 0; i < 8; i++) {
            long m = bm + ty * 8 + i;
            float* Crow = out + m * (long)H_DIM + bn + tx * 8;
            float2 c0 = unpack2(acc[i][0]), c1 = unpack2(acc[i][1]);
            float2 c2 = unpack2(acc[i][2]), c3 = unpack2(acc[i][3]);
            *(float4*)(Crow)     = make_float4(c0.x + bv[0], c0.y + bv[1], c1.x + bv[2], c1.y + bv[3]);
            *(float4*)(Crow + 4) = make_float4(c2.x + bv[4], c2.y + bv[5], c3.x + bv[6], c3.y + bv[7]);
        }

        __threadfence();
        __syncthreads();
        if (t == 0) atomicAdd(&g_flags[b][s_chunk], 1);
        return;
    }

    // ====================== recurrence (warp-specialized) =================
    float (*hS)[128]   = (float(*)[128])(arena);          // [buf][jl] my h half
    float (*pbuf)[128] = (float(*)[128])(arena + 1024);   // incoming peer partials
    unsigned long long* mbarp = (unsigned long long*)(arena + 2048);

    const int rank = blockIdx.x;
    const int row  = blockIdx.y;
    const bool isA = (t < 128);           // P-warps ship; L-warps finish
    const int jl   = isA ? t : t - 128;   // 0..127
    const int jg   = rank * 128 + jl;            // my output column
    const int jp   = (rank ^ 1) * 128 + jl;      // peer output I help with

    // --- preload 128 weights (64 regs): A -> peer row, B -> own row; my k-half
    unsigned long long w[64];
    {
        const float* wr = Wh + (long)(isA ? jp : jg) * H_DIM + rank * 128;
#pragma unroll
        for (int u = 0; u < 32; u++) {
            ulonglong2 a = *(const ulonglong2*)(wr + u * 4);
            w[2 * u]     = a.x;
            w[2 * u + 1] = a.y;
        }
    }

    const uint32_t mb0 = smem_u32(&mbarp[0]);
    const uint32_t mb1 = smem_u32(&mbarp[1]);

    if (t == 0) {
        mbar_init(mb0, 1);
        mbar_init(mb1, 1);
        mbar_expect_tx(mb0, 512);
        mbar_expect_tx(mb1, 512);
    }
    if (t < 128) hS[0][t] = 0.0f;     // h0 = 0
    __syncthreads();
    asm volatile("barrier.cluster.arrive.aligned;" ::: "memory");
    asm volatile("barrier.cluster.wait.aligned;" ::: "memory");

    const uint32_t prB0 = mapa_u32(smem_u32(&pbuf[0][0]), rank ^ 1);
    const uint32_t prB1 = mapa_u32(smem_u32(&pbuf[1][0]), rank ^ 1);
    const uint32_t pmb0 = mapa_u32(mb0, rank ^ 1);
    const uint32_t pmb1 = mapa_u32(mb1, rank ^ 1);
    const uint32_t shipoff = (uint32_t)jl * 4u;

    // wait for xw chunk 0 (t0 spins, block follows)
    {
        if (t == 0) {
            volatile int* f = &g_flags[row][0];
            while (*f < 2) __nanosleep(512);
        }
        __syncthreads();
        __threadfence();
    }

    float* xwp = out + (long)row * S_LEN * H_DIM + jg;
    float xw_next = xwp[0];

    for (int step = 0; step < S_LEN; step++) {
        const int b = step & 1;

        // ---- full 128-k dot from local h (32x broadcast LDS.128) ----
        const ulonglong2* h2 = (const ulonglong2*)&hS[b][0];
        unsigned long long a0 = 0ull, a1 = 0ull, a2 = 0ull, a3 = 0ull;
#pragma unroll
        for (int u = 0; u < 32; u += 2) {            // h2[0..31] = 128 floats
            ulonglong2 hv0 = h2[u], hv1 = h2[u + 1];
            a0 = ffma2(hv0.x, w[2 * u], a0);
            a1 = ffma2(hv0.y, w[2 * u + 1], a1);
            a2 = ffma2(hv1.x, w[2 * u + 2], a2);
            a3 = ffma2(hv1.y, w[2 * u + 3], a3);
        }
        float2 f0 = unpack2(a0), f1 = unpack2(a1);
        float2 f2 = unpack2(a2), f3 = unpack2(a3);
        float S = ((f0.x + f0.y) + (f1.x + f1.y)) +
                  ((f2.x + f2.y) + (f3.x + f3.y));

        if (isA) {
            // ship peer partial immediately; nothing else on this path
            st_async_f32((b ? prB1 : prB0) + shipoff, S, b ? pmb1 : pmb0);
        } else {
            // finish own output: wait for peer partial, combine, store
            mbar_wait(b ? mb1 : mb0, (step >> 1) & 1);
            if (t == 128) mbar_expect_tx(b ? mb1 : mb0, 512);  // re-arm step+2

            float v = tanh_fast(S + pbuf[b][jl] + xw_next);
            hS[b ^ 1][jl] = v;                       // h(step+1)
            xwp[(long)step * H_DIM] = v;             // in-place output
            if (step == S_LEN - 1)
                out[(long)B_DIM * S_LEN * H_DIM + (long)row * H_DIM + jg] = v;
        }

        __syncthreads();                             // h(step+1) visible

        // chunk gate + xw prefetch for step+1 (uniform control flow)
        if (step + 1 < S_LEN) {
            if (((step + 1) & (CHUNK - 1)) == 0) {
                if (t == 0) {
                    volatile int* f = &g_flags[row][(step + 1) >> 7];
                    while (*f < 2) __nanosleep(512);
                }
                __syncthreads();
                __threadfence();
            }
            if (!isA) xw_next = xwp[(long)(step + 1) * H_DIM];
        }
    }

    asm volatile("barrier.cluster.arrive.aligned;" ::: "memory");
    asm volatile("barrier.cluster.wait.aligned;" ::: "memory");
}

// ---------------------------------------------------------------------------
// Launch
// ---------------------------------------------------------------------------
extern "C" void kernel_launch(void* const* d_in, const int* in_sizes, int n_in,
                              void* d_out, int out_size) {
    const float* x    = (const float*)d_in[0];  // [B,S,I]
    const float* Wx_w = (const float*)d_in[1];  // [H,I]
    const float* Wx_b = (const float*)d_in[2];  // [H]
    const float* Wh_w = (const float*)d_in[3];  // [H,H]
    float* out = (float*)d_out;                 // [B,S,H] ++ [B,H]

    flag_init_kernel<<<1, 512>>>();

    dim3 g(2, REC_Y + GEMM_MT);                 // (2, 544)
    srnn_fused_kernel<<<g, 256>>>(x, Wx_w, Wx_b, Wh_w, out);
}